// round 12
// baseline (speedup 1.0000x reference)
#include <cuda_runtime.h>
#include <cuda_fp16.h>

#define NMAX 100000
#define EMAX 1600000
#define HID 64
#define SCAN_CHUNK 1024   // elements per scan block (256 thr * 4)

// scratch (no cudaMalloc allowed)
__device__ __align__(16) __half g_xp [NMAX * HID];   // fp16 message payload
__device__ __align__(16) float  g_h  [NMAX * HID];
__device__ float g_als[NMAX * 2];
__device__ float g_ald[NMAX * 2];
__device__ float g_w  [EMAX * 2];      // per-edge softmax weight, both heads
__device__ int   g_cnt[NMAX];
__device__ int   g_off[NMAX + 1];
__device__ int   g_cur[NMAX];
__device__ int   g_srcs[EMAX];
__device__ int   g_dstp[EMAX];         // CSR-position -> dst node
__device__ int   g_bsums[(NMAX + SCAN_CHUNK - 1) / SCAN_CHUNK];
__device__ int   g_boff [(NMAX + SCAN_CHUNK - 1) / SCAN_CHUNK];
__device__ int   g_is64;

// ---------------------------------------------------------------------------
// Detect whether edge_index is stored as int64 (high words zero) or int32.
// ---------------------------------------------------------------------------
__global__ __launch_bounds__(256)
void detect_kernel(const int* __restrict__ ei)
{
    __shared__ int s_or;
    if (threadIdx.x == 0) s_or = 0;
    __syncthreads();
    int o = 0;
    for (int i = threadIdx.x; i < 2048; i += 256)
        o |= ei[2 * i + 1];
    if (o) atomicOr(&s_or, 1);
    __syncthreads();
    if (threadIdx.x == 0) g_is64 = (s_or == 0) ? 1 : 0;
}

__device__ __forceinline__ int load_src(const int* ei, int E, int i, int is64)
{
    return is64 ? ei[2 * i] : ei[i];
}
__device__ __forceinline__ int load_dst(const int* ei, int E, int i, int is64)
{
    return is64 ? ei[2 * E + 2 * i] : ei[E + i];
}

// ---------------------------------------------------------------------------
// CSR build (by destination). Only integer atomics.
// ---------------------------------------------------------------------------
__global__ __launch_bounds__(256)
void zero_cnt_kernel(int n)
{
    int i = blockIdx.x * blockDim.x + threadIdx.x;
    if (i < n) g_cnt[i] = 0;
}

__global__ __launch_bounds__(256)
void hist_kernel(const int* __restrict__ ei, int E)
{
    int i = blockIdx.x * blockDim.x + threadIdx.x;
    int is64 = g_is64;
    if (i < E) atomicAdd(&g_cnt[load_dst(ei, E, i, is64)], 1);
}

__device__ __forceinline__ int block_exscan256(int v, int* sh)
{
    const int t = threadIdx.x;
    sh[t] = v;
    __syncthreads();
#pragma unroll
    for (int off = 1; off < 256; off <<= 1) {
        int u = (t >= off) ? sh[t - off] : 0;
        __syncthreads();
        sh[t] += u;
        __syncthreads();
    }
    return sh[t] - v;
}

__global__ __launch_bounds__(256)
void scan_partial(int n)
{
    __shared__ int sh[256];
    const int t = threadIdx.x;
    const int base = blockIdx.x * SCAN_CHUNK + t * 4;
    int s = 0;
#pragma unroll
    for (int j = 0; j < 4; j++)
        if (base + j < n) s += g_cnt[base + j];
    sh[t] = s;
    __syncthreads();
    for (int off = 128; off; off >>= 1) {
        if (t < off) sh[t] += sh[t + off];
        __syncthreads();
    }
    if (t == 0) g_bsums[blockIdx.x] = sh[0];
}

__global__ __launch_bounds__(256)
void scan_bsums(int nb)
{
    __shared__ int sh[256];
    const int t = threadIdx.x;
    int v = (t < nb) ? g_bsums[t] : 0;
    int ex = block_exscan256(v, sh);
    if (t < nb) g_boff[t] = ex;
}

__global__ __launch_bounds__(256)
void scan_final(int n, int E)
{
    __shared__ int sh[256];
    const int t = threadIdx.x;
    const int base = blockIdx.x * SCAN_CHUNK + t * 4;
    int c[4];
    int s = 0;
#pragma unroll
    for (int j = 0; j < 4; j++) {
        c[j] = (base + j < n) ? g_cnt[base + j] : 0;
        s += c[j];
    }
    int ex = block_exscan256(s, sh) + g_boff[blockIdx.x];
#pragma unroll
    for (int j = 0; j < 4; j++) {
        if (base + j < n) {
            g_off[base + j] = ex;
            g_cur[base + j] = ex;
        }
        ex += c[j];
    }
    if (blockIdx.x == 0 && t == 0) g_off[n] = E;
}

__global__ __launch_bounds__(256)
void scatter_kernel(const int* __restrict__ ei, int E)
{
    int i = blockIdx.x * blockDim.x + threadIdx.x;
    if (i >= E) return;
    int is64 = g_is64;
    int d = load_dst(ei, E, i, is64);
    int s = load_src(ei, E, i, is64);
    int pos = atomicAdd(&g_cur[d], 1);
    g_srcs[pos] = s;
    g_dstp[pos] = d;
}

// ---------------------------------------------------------------------------
// Per-edge softmax weights for both heads (CSR order). Thread per edge,
// fully parallel, removes dependent logit load + exp from the gather chain.
// ---------------------------------------------------------------------------
__global__ __launch_bounds__(256)
void edge_w_kernel(int E)
{
    int i = blockIdx.x * blockDim.x + threadIdx.x;
    if (i >= E) return;
    int s = g_srcs[i];
    int d = g_dstp[i];
    float2 as_ = *(const float2*)&g_als[s * 2];
    float2 ad_ = *(const float2*)&g_ald[d * 2];
    float t0 = as_.x + ad_.x; t0 = fmaxf(t0, 0.2f * t0);
    float t1 = as_.y + ad_.y; t1 = fmaxf(t1, 0.2f * t1);
    *(float2*)&g_w[i * 2] = make_float2(__expf(t0), __expf(t1));
}

// ---------------------------------------------------------------------------
// Fused GEMM + attention-logit epilogue. xp stored as fp16 (gather payload);
// logits computed from fp32 accumulators.
// ---------------------------------------------------------------------------
template<int K, bool FIRST>
__global__ __launch_bounds__(256)
void gemm_al_kernel(const float* __restrict__ Xin,
                    const float* __restrict__ W,
                    const float* __restrict__ att_s,
                    const float* __restrict__ att_d,
                    int n)
{
    const float* __restrict__ X = FIRST ? Xin : g_h;

    __shared__ __align__(16) float sW[64 * 64];
    __shared__ __align__(16) float sXT[64][132];

    const int tid = threadIdx.x;
    const int cx  = tid & 15;
    const int ry  = tid >> 4;
    const int row0 = blockIdx.x * 128;

    float C[8][4];
#pragma unroll
    for (int i = 0; i < 8; i++)
#pragma unroll
        for (int j = 0; j < 4; j++) C[i][j] = 0.f;

    for (int kc = 0; kc < K; kc += 64) {
        __syncthreads();
#pragma unroll
        for (int q = 0; q < 4; q++) {
            int idx4 = tid + q * 256;
            float4 v = *(const float4*)&W[kc * 64 + idx4 * 4];
            *(float4*)&sW[idx4 * 4] = v;
        }
#pragma unroll
        for (int q = 0; q < 8; q++) {
            int lin = tid + q * 256;
            int r  = lin >> 4;
            int c4 = lin & 15;
            int gr = row0 + r; if (gr > n - 1) gr = n - 1;
            float4 v = *(const float4*)&X[(long long)gr * K + kc + c4 * 4];
            sXT[c4 * 4 + 0][r] = v.x;
            sXT[c4 * 4 + 1][r] = v.y;
            sXT[c4 * 4 + 2][r] = v.z;
            sXT[c4 * 4 + 3][r] = v.w;
        }
        __syncthreads();
#pragma unroll
        for (int k = 0; k < 64; k++) {
            float4 wv = *(const float4*)&sW[k * 64 + cx * 4];
            float4 xa = *(const float4*)&sXT[k][ry * 8];
            float4 xb = *(const float4*)&sXT[k][ry * 8 + 4];
            float xr[8] = {xa.x, xa.y, xa.z, xa.w, xb.x, xb.y, xb.z, xb.w};
#pragma unroll
            for (int i = 0; i < 8; i++) {
                C[i][0] = fmaf(xr[i], wv.x, C[i][0]);
                C[i][1] = fmaf(xr[i], wv.y, C[i][1]);
                C[i][2] = fmaf(xr[i], wv.z, C[i][2]);
                C[i][3] = fmaf(xr[i], wv.w, C[i][3]);
            }
        }
    }

    const int h    = cx >> 3;
    const int lane = tid & 31;
    float asv[4], adv[4];
#pragma unroll
    for (int j = 0; j < 4; j++) {
        asv[j] = __ldg(&att_s[cx * 4 + j]);
        adv[j] = __ldg(&att_d[cx * 4 + j]);
    }

#pragma unroll
    for (int i = 0; i < 8; i++) {
        float als = 0.f, ald = 0.f;
#pragma unroll
        for (int j = 0; j < 4; j++) {
            als = fmaf(C[i][j], asv[j], als);
            ald = fmaf(C[i][j], adv[j], ald);
        }
#pragma unroll
        for (int off = 4; off; off >>= 1) {
            als += __shfl_down_sync(0xffffffffu, als, off, 8);
            ald += __shfl_down_sync(0xffffffffu, ald, off, 8);
        }
        int row = row0 + ry * 8 + i;
        if (row < n) {
            if ((lane & 7) == 0) {
                g_als[row * 2 + h] = als;
                g_ald[row * 2 + h] = ald;
            }
            __half2 p0 = __floats2half2_rn(C[i][0], C[i][1]);
            __half2 p1 = __floats2half2_rn(C[i][2], C[i][3]);
            __half2* dst = reinterpret_cast<__half2*>(&g_xp[row * HID + cx * 4]);
            dst[0] = p0;
            dst[1] = p1;
        }
    }
}

// ---------------------------------------------------------------------------
// Gather pass v4: one warp per destination node, half-warp per head.
// Edge weights precomputed -> block front is two independent coalesced LDGs,
// and the NEXT block's (sidx, w) is prefetched before the inner FMA loop.
// ---------------------------------------------------------------------------
template<bool LAST>
__global__ __launch_bounds__(256)
void gather_kernel(const float* __restrict__ bias,
                   float* __restrict__ out, int n)
{
    int warp = (blockIdx.x * 256 + threadIdx.x) >> 5;
    int lane = threadIdx.x & 31;
    if (warp >= n) return;
    const int node = warp;
    const int h  = lane >> 4;           // half-warp = head
    const int hl = lane & 15;           // lane within half

    const __half2* __restrict__ xp2 =
        reinterpret_cast<const __half2*>(g_xp) + lane;  // + 32*s per row

    // self loop
    float t0 = __ldg(&g_als[node * 2 + h]) + __ldg(&g_ald[node * 2 + h]);
    t0 = fmaxf(t0, 0.2f * t0);
    float wself = __expf(t0);
    float2 xv = __half22float2(xp2[node * 32]);
    float a0 = xv.x * wself, a1 = xv.y * wself;
    float segl = 0.f;

    const int beg = g_off[node];
    const int end = g_off[node + 1];

    // prime first block
    int idx = beg + hl;
    int   sidx_n = 0;
    float w_n    = 0.f;
    if (idx < end) {
        sidx_n = __ldg(&g_srcs[idx]);
        w_n    = __ldg(&g_w[idx * 2 + h]);
    }

    for (int i = beg; i < end; i += 16) {
        int   sidx = sidx_n;
        float w    = w_n;

        // prefetch next block
        int idx2 = i + 16 + hl;
        sidx_n = 0; w_n = 0.f;
        if (idx2 < end) {
            sidx_n = __ldg(&g_srcs[idx2]);
            w_n    = __ldg(&g_w[idx2 * 2 + h]);
        }

        segl += w;

#pragma unroll
        for (int jb = 0; jb < 16; jb += 8) {
            float  ww[8];
            float2 xs[8];
#pragma unroll
            for (int j = 0; j < 8; j++) {
                ww[j] = __shfl_sync(0xffffffffu, w,    jb + j, 16);
                int s = __shfl_sync(0xffffffffu, sidx, jb + j, 16);
                xs[j] = __half22float2(xp2[s * 32]);
            }
#pragma unroll
            for (int j = 0; j < 8; j++) {
                a0 = fmaf(xs[j].x, ww[j], a0);
                a1 = fmaf(xs[j].y, ww[j], a1);
            }
        }
    }

#pragma unroll
    for (int off = 8; off; off >>= 1)
        segl += __shfl_xor_sync(0xffffffffu, segl, off, 16);
    float seg = segl + wself;

    float inv = 1.f / (seg + 1e-16f);
    float2 bv = *(const float2*)&bias[lane * 2];
    float v0 = a0 * inv + bv.x;
    float v1 = a1 * inv + bv.y;
    if (!LAST) {
        v0 = v0 > 0.f ? v0 : expm1f(v0);
        v1 = v1 > 0.f ? v1 : expm1f(v1);
        *(float2*)&g_h[node * HID + lane * 2] = make_float2(v0, v1);
    } else {
        *(float2*)&out[node * HID + lane * 2] = make_float2(v0, v1);
    }
}

extern "C" void kernel_launch(void* const* d_in, const int* in_sizes, int n_in,
                              void* d_out, int out_size)
{
    const float* x   = (const float*)d_in[0];
    const int*   ei  = (const int*)d_in[1];
    const float* W1  = (const float*)d_in[2];
    const float* as1 = (const float*)d_in[3];
    const float* ad1 = (const float*)d_in[4];
    const float* b1  = (const float*)d_in[5];
    const float* W2  = (const float*)d_in[6];
    const float* as2 = (const float*)d_in[7];
    const float* ad2 = (const float*)d_in[8];
    const float* b2  = (const float*)d_in[9];

    const int n = in_sizes[0] / 128;          // 100000
    const int E = in_sizes[1] / 2;            // 1600000
    const int gb  = (n + 127) / 128;
    const int nbl = (n + 255) / 256;
    const int ebl = (E + 255) / 256;
    const int wbl = ((n * 32) + 255) / 256;
    const int sb  = (n + SCAN_CHUNK - 1) / SCAN_CHUNK;

    static cudaStream_t sCsr = nullptr, sMain = nullptr;
    static cudaEvent_t evFork = nullptr, evCsr = nullptr, evDone = nullptr;
    if (!sCsr) {
        cudaStreamCreateWithFlags(&sCsr,  cudaStreamNonBlocking);
        cudaStreamCreateWithFlags(&sMain, cudaStreamNonBlocking);
        cudaEventCreateWithFlags(&evFork, cudaEventDisableTiming);
        cudaEventCreateWithFlags(&evCsr,  cudaEventDisableTiming);
        cudaEventCreateWithFlags(&evDone, cudaEventDisableTiming);
    }

    cudaEventRecord(evFork, 0);
    cudaStreamWaitEvent(sCsr,  evFork, 0);
    cudaStreamWaitEvent(sMain, evFork, 0);

    detect_kernel<<<1, 256, 0, sCsr>>>(ei);
    zero_cnt_kernel<<<nbl, 256, 0, sCsr>>>(n);
    hist_kernel<<<ebl, 256, 0, sCsr>>>(ei, E);
    gemm_al_kernel<128, true><<<gb, 256, 0, sMain>>>(x, W1, as1, ad1, n);
    scan_partial<<<sb, 256, 0, sCsr>>>(n);
    scan_bsums<<<1, 256, 0, sCsr>>>(sb);
    scan_final<<<sb, 256, 0, sCsr>>>(n, E);
    scatter_kernel<<<ebl, 256, 0, sCsr>>>(ei, E);
    cudaEventRecord(evCsr, sCsr);

    cudaStreamWaitEvent(sMain, evCsr, 0);
    // layer 1
    edge_w_kernel<<<ebl, 256, 0, sMain>>>(E);
    gather_kernel<false><<<wbl, 256, 0, sMain>>>(b1, nullptr, n);
    // layer 2
    gemm_al_kernel<64, false><<<gb, 256, 0, sMain>>>(x, W2, as2, ad2, n);
    edge_w_kernel<<<ebl, 256, 0, sMain>>>(E);
    gather_kernel<true><<<wbl, 256, 0, sMain>>>(b2, (float*)d_out, n);

    cudaEventRecord(evDone, sMain);
    cudaStreamWaitEvent(0, evDone, 0);
}

// round 13
// speedup vs baseline: 1.0469x; 1.0469x over previous
#include <cuda_runtime.h>
#include <cuda_fp16.h>

#define NMAX 100000
#define EMAX 1600000
#define HID 64
#define SCAN_CHUNK 1024   // elements per scan block (256 thr * 4)

// scratch (no cudaMalloc allowed)
__device__ __align__(16) __half g_xp [NMAX * HID];   // fp16 message payload
__device__ __align__(16) float  g_h  [NMAX * HID];
__device__ float g_als[NMAX * 2];
__device__ float g_ald[NMAX * 2];
__device__ int   g_cnt[NMAX];
__device__ int   g_off[NMAX + 1];
__device__ int   g_cur[NMAX];
__device__ int   g_srcs[EMAX];
__device__ int   g_bsums[(NMAX + SCAN_CHUNK - 1) / SCAN_CHUNK];
__device__ int   g_boff [(NMAX + SCAN_CHUNK - 1) / SCAN_CHUNK];
__device__ int   g_is64;

// ---------------------------------------------------------------------------
// Detect whether edge_index is stored as int64 (high words zero) or int32.
// ---------------------------------------------------------------------------
__global__ __launch_bounds__(256)
void detect_kernel(const int* __restrict__ ei)
{
    __shared__ int s_or;
    if (threadIdx.x == 0) s_or = 0;
    __syncthreads();
    int o = 0;
    for (int i = threadIdx.x; i < 2048; i += 256)
        o |= ei[2 * i + 1];
    if (o) atomicOr(&s_or, 1);
    __syncthreads();
    if (threadIdx.x == 0) g_is64 = (s_or == 0) ? 1 : 0;
}

__device__ __forceinline__ int load_src(const int* ei, int E, int i, int is64)
{
    return is64 ? ei[2 * i] : ei[i];
}
__device__ __forceinline__ int load_dst(const int* ei, int E, int i, int is64)
{
    return is64 ? ei[2 * E + 2 * i] : ei[E + i];
}

// ---------------------------------------------------------------------------
// CSR build (by destination). Only integer atomics.
// ---------------------------------------------------------------------------
__global__ __launch_bounds__(256)
void zero_cnt_kernel(int n)
{
    int i = blockIdx.x * blockDim.x + threadIdx.x;
    if (i < n) g_cnt[i] = 0;
}

__global__ __launch_bounds__(256)
void hist_kernel(const int* __restrict__ ei, int E)
{
    int i = blockIdx.x * blockDim.x + threadIdx.x;
    int is64 = g_is64;
    if (i < E) atomicAdd(&g_cnt[load_dst(ei, E, i, is64)], 1);
}

__device__ __forceinline__ int block_exscan256(int v, int* sh)
{
    const int t = threadIdx.x;
    sh[t] = v;
    __syncthreads();
#pragma unroll
    for (int off = 1; off < 256; off <<= 1) {
        int u = (t >= off) ? sh[t - off] : 0;
        __syncthreads();
        sh[t] += u;
        __syncthreads();
    }
    return sh[t] - v;
}

__global__ __launch_bounds__(256)
void scan_partial(int n)
{
    __shared__ int sh[256];
    const int t = threadIdx.x;
    const int base = blockIdx.x * SCAN_CHUNK + t * 4;
    int s = 0;
#pragma unroll
    for (int j = 0; j < 4; j++)
        if (base + j < n) s += g_cnt[base + j];
    sh[t] = s;
    __syncthreads();
    for (int off = 128; off; off >>= 1) {
        if (t < off) sh[t] += sh[t + off];
        __syncthreads();
    }
    if (t == 0) g_bsums[blockIdx.x] = sh[0];
}

__global__ __launch_bounds__(256)
void scan_bsums(int nb)
{
    __shared__ int sh[256];
    const int t = threadIdx.x;
    int v = (t < nb) ? g_bsums[t] : 0;
    int ex = block_exscan256(v, sh);
    if (t < nb) g_boff[t] = ex;
}

__global__ __launch_bounds__(256)
void scan_final(int n, int E)
{
    __shared__ int sh[256];
    const int t = threadIdx.x;
    const int base = blockIdx.x * SCAN_CHUNK + t * 4;
    int c[4];
    int s = 0;
#pragma unroll
    for (int j = 0; j < 4; j++) {
        c[j] = (base + j < n) ? g_cnt[base + j] : 0;
        s += c[j];
    }
    int ex = block_exscan256(s, sh) + g_boff[blockIdx.x];
#pragma unroll
    for (int j = 0; j < 4; j++) {
        if (base + j < n) {
            g_off[base + j] = ex;
            g_cur[base + j] = ex;
        }
        ex += c[j];
    }
    if (blockIdx.x == 0 && t == 0) g_off[n] = E;
}

__global__ __launch_bounds__(256)
void scatter_kernel(const int* __restrict__ ei, int E)
{
    int i = blockIdx.x * blockDim.x + threadIdx.x;
    if (i >= E) return;
    int is64 = g_is64;
    int d = load_dst(ei, E, i, is64);
    int s = load_src(ei, E, i, is64);
    int pos = atomicAdd(&g_cur[d], 1);
    g_srcs[pos] = s;
}

// ---------------------------------------------------------------------------
// Fused GEMM + attention-logit epilogue. xp stored as fp16 (gather payload);
// logits computed from fp32 accumulators.
// ---------------------------------------------------------------------------
template<int K, bool FIRST>
__global__ __launch_bounds__(256)
void gemm_al_kernel(const float* __restrict__ Xin,
                    const float* __restrict__ W,
                    const float* __restrict__ att_s,
                    const float* __restrict__ att_d,
                    int n)
{
    const float* __restrict__ X = FIRST ? Xin : g_h;

    __shared__ __align__(16) float sW[64 * 64];
    __shared__ __align__(16) float sXT[64][132];

    const int tid = threadIdx.x;
    const int cx  = tid & 15;
    const int ry  = tid >> 4;
    const int row0 = blockIdx.x * 128;

    float C[8][4];
#pragma unroll
    for (int i = 0; i < 8; i++)
#pragma unroll
        for (int j = 0; j < 4; j++) C[i][j] = 0.f;

    for (int kc = 0; kc < K; kc += 64) {
        __syncthreads();
#pragma unroll
        for (int q = 0; q < 4; q++) {
            int idx4 = tid + q * 256;
            float4 v = *(const float4*)&W[kc * 64 + idx4 * 4];
            *(float4*)&sW[idx4 * 4] = v;
        }
#pragma unroll
        for (int q = 0; q < 8; q++) {
            int lin = tid + q * 256;
            int r  = lin >> 4;
            int c4 = lin & 15;
            int gr = row0 + r; if (gr > n - 1) gr = n - 1;
            float4 v = *(const float4*)&X[(long long)gr * K + kc + c4 * 4];
            sXT[c4 * 4 + 0][r] = v.x;
            sXT[c4 * 4 + 1][r] = v.y;
            sXT[c4 * 4 + 2][r] = v.z;
            sXT[c4 * 4 + 3][r] = v.w;
        }
        __syncthreads();
#pragma unroll
        for (int k = 0; k < 64; k++) {
            float4 wv = *(const float4*)&sW[k * 64 + cx * 4];
            float4 xa = *(const float4*)&sXT[k][ry * 8];
            float4 xb = *(const float4*)&sXT[k][ry * 8 + 4];
            float xr[8] = {xa.x, xa.y, xa.z, xa.w, xb.x, xb.y, xb.z, xb.w};
#pragma unroll
            for (int i = 0; i < 8; i++) {
                C[i][0] = fmaf(xr[i], wv.x, C[i][0]);
                C[i][1] = fmaf(xr[i], wv.y, C[i][1]);
                C[i][2] = fmaf(xr[i], wv.z, C[i][2]);
                C[i][3] = fmaf(xr[i], wv.w, C[i][3]);
            }
        }
    }

    const int h    = cx >> 3;
    const int lane = tid & 31;
    float asv[4], adv[4];
#pragma unroll
    for (int j = 0; j < 4; j++) {
        asv[j] = __ldg(&att_s[cx * 4 + j]);
        adv[j] = __ldg(&att_d[cx * 4 + j]);
    }

#pragma unroll
    for (int i = 0; i < 8; i++) {
        float als = 0.f, ald = 0.f;
#pragma unroll
        for (int j = 0; j < 4; j++) {
            als = fmaf(C[i][j], asv[j], als);
            ald = fmaf(C[i][j], adv[j], ald);
        }
#pragma unroll
        for (int off = 4; off; off >>= 1) {
            als += __shfl_down_sync(0xffffffffu, als, off, 8);
            ald += __shfl_down_sync(0xffffffffu, ald, off, 8);
        }
        int row = row0 + ry * 8 + i;
        if (row < n) {
            if ((lane & 7) == 0) {
                g_als[row * 2 + h] = als;
                g_ald[row * 2 + h] = ald;
            }
            __half2 p0 = __floats2half2_rn(C[i][0], C[i][1]);
            __half2 p1 = __floats2half2_rn(C[i][2], C[i][3]);
            __half2* dst = reinterpret_cast<__half2*>(&g_xp[row * HID + cx * 4]);
            dst[0] = p0;
            dst[1] = p1;
        }
    }
}

// ---------------------------------------------------------------------------
// Gather pass v5: one warp per destination node, half-warp per head.
// Inline weight computation (R11) + cross-iteration pipelining: next block's
// sidx AND dependent als load are issued during the current block's FMA work.
// ---------------------------------------------------------------------------
template<bool LAST>
__global__ __launch_bounds__(256)
void gather_kernel(const float* __restrict__ bias,
                   float* __restrict__ out, int n)
{
    int warp = (blockIdx.x * 256 + threadIdx.x) >> 5;
    int lane = threadIdx.x & 31;
    if (warp >= n) return;
    const int node = warp;
    const int h  = lane >> 4;           // half-warp = head
    const int hl = lane & 15;           // lane within half

    const __half2* __restrict__ xp2 =
        reinterpret_cast<const __half2*>(g_xp) + lane;  // + 32*s per row

    const float ald_h = __ldg(&g_ald[node * 2 + h]);

    // self loop
    float t0 = __ldg(&g_als[node * 2 + h]) + ald_h;
    t0 = fmaxf(t0, 0.2f * t0);
    float wself = __expf(t0);
    float2 xv = __half22float2(xp2[node * 32]);
    float a0 = xv.x * wself, a1 = xv.y * wself;
    float segl = 0.f;

    const int beg = g_off[node];
    const int end = g_off[node + 1];

    // prime first block: sidx + dependent als
    int   sidx_n = 0;
    float al_n   = 0.f;
    bool  val_n  = (beg + hl) < end;
    if (val_n) {
        sidx_n = __ldg(&g_srcs[beg + hl]);
        al_n   = __ldg(&g_als[sidx_n * 2 + h]);
    }

    for (int i = beg; i < end; i += 16) {
        int   sidx  = sidx_n;
        float al    = al_n;
        bool  valid = val_n;

        // weight for current block (off the LDG critical path)
        float tt = al + ald_h;
        tt = fmaxf(tt, 0.2f * tt);
        float w = valid ? __expf(tt) : 0.f;
        segl += w;

        // prefetch next block's sidx + als under the FMA phases below
        int idx2 = i + 16 + hl;
        val_n = idx2 < end;
        sidx_n = 0; al_n = 0.f;
        if (val_n) {
            sidx_n = __ldg(&g_srcs[idx2]);
            al_n   = __ldg(&g_als[sidx_n * 2 + h]);
        }

#pragma unroll
        for (int jb = 0; jb < 16; jb += 8) {
            float  ww[8];
            float2 xs[8];
#pragma unroll
            for (int j = 0; j < 8; j++) {
                ww[j] = __shfl_sync(0xffffffffu, w,    jb + j, 16);
                int s = __shfl_sync(0xffffffffu, sidx, jb + j, 16);
                xs[j] = __half22float2(xp2[s * 32]);
            }
#pragma unroll
            for (int j = 0; j < 8; j++) {
                a0 = fmaf(xs[j].x, ww[j], a0);
                a1 = fmaf(xs[j].y, ww[j], a1);
            }
        }
    }

#pragma unroll
    for (int off = 8; off; off >>= 1)
        segl += __shfl_xor_sync(0xffffffffu, segl, off, 16);
    float seg = segl + wself;

    float inv = 1.f / (seg + 1e-16f);
    float2 bv = *(const float2*)&bias[lane * 2];
    float v0 = a0 * inv + bv.x;
    float v1 = a1 * inv + bv.y;
    if (!LAST) {
        v0 = v0 > 0.f ? v0 : expm1f(v0);
        v1 = v1 > 0.f ? v1 : expm1f(v1);
        *(float2*)&g_h[node * HID + lane * 2] = make_float2(v0, v1);
    } else {
        *(float2*)&out[node * HID + lane * 2] = make_float2(v0, v1);
    }
}

extern "C" void kernel_launch(void* const* d_in, const int* in_sizes, int n_in,
                              void* d_out, int out_size)
{
    const float* x   = (const float*)d_in[0];
    const int*   ei  = (const int*)d_in[1];
    const float* W1  = (const float*)d_in[2];
    const float* as1 = (const float*)d_in[3];
    const float* ad1 = (const float*)d_in[4];
    const float* b1  = (const float*)d_in[5];
    const float* W2  = (const float*)d_in[6];
    const float* as2 = (const float*)d_in[7];
    const float* ad2 = (const float*)d_in[8];
    const float* b2  = (const float*)d_in[9];

    const int n = in_sizes[0] / 128;          // 100000
    const int E = in_sizes[1] / 2;            // 1600000
    const int gb  = (n + 127) / 128;
    const int nbl = (n + 255) / 256;
    const int ebl = (E + 255) / 256;
    const int wbl = ((n * 32) + 255) / 256;
    const int sb  = (n + SCAN_CHUNK - 1) / SCAN_CHUNK;

    static cudaStream_t sCsr = nullptr, sMain = nullptr;
    static cudaEvent_t evFork = nullptr, evCsr = nullptr, evDone = nullptr;
    if (!sCsr) {
        cudaStreamCreateWithFlags(&sCsr,  cudaStreamNonBlocking);
        cudaStreamCreateWithFlags(&sMain, cudaStreamNonBlocking);
        cudaEventCreateWithFlags(&evFork, cudaEventDisableTiming);
        cudaEventCreateWithFlags(&evCsr,  cudaEventDisableTiming);
        cudaEventCreateWithFlags(&evDone, cudaEventDisableTiming);
    }

    cudaEventRecord(evFork, 0);
    cudaStreamWaitEvent(sCsr,  evFork, 0);
    cudaStreamWaitEvent(sMain, evFork, 0);

    detect_kernel<<<1, 256, 0, sCsr>>>(ei);
    zero_cnt_kernel<<<nbl, 256, 0, sCsr>>>(n);
    hist_kernel<<<ebl, 256, 0, sCsr>>>(ei, E);
    gemm_al_kernel<128, true><<<gb, 256, 0, sMain>>>(x, W1, as1, ad1, n);
    scan_partial<<<sb, 256, 0, sCsr>>>(n);
    scan_bsums<<<1, 256, 0, sCsr>>>(sb);
    scan_final<<<sb, 256, 0, sCsr>>>(n, E);
    scatter_kernel<<<ebl, 256, 0, sCsr>>>(ei, E);
    cudaEventRecord(evCsr, sCsr);

    cudaStreamWaitEvent(sMain, evCsr, 0);
    gather_kernel<false><<<wbl, 256, 0, sMain>>>(b1, nullptr, n);
    gemm_al_kernel<64, false><<<gb, 256, 0, sMain>>>(x, W2, as2, ad2, n);
    gather_kernel<true><<<wbl, 256, 0, sMain>>>(b2, (float*)d_out, n);

    cudaEventRecord(evDone, sMain);
    cudaStreamWaitEvent(0, evDone, 0);
}

// round 15
// speedup vs baseline: 1.0987x; 1.0495x over previous
#include <cuda_runtime.h>
#include <cuda_fp16.h>

#define NMAX 100000
#define EMAX 1600000
#define HID 64
#define SCAN_CHUNK 1024   // elements per scan block (256 thr * 4)

// scratch (no cudaMalloc allowed) — double-buffered per layer
__device__ __align__(16) __half g_xp1 [NMAX * HID];
__device__ __align__(16) __half g_xp2 [NMAX * HID];
__device__ __align__(16) float  g_h   [NMAX * HID];
__device__ float g_als1[NMAX * 2];
__device__ float g_ald1[NMAX * 2];
__device__ float g_als2[NMAX * 2];
__device__ float g_ald2[NMAX * 2];
__device__ int   g_cnt[NMAX];
__device__ int   g_off[NMAX + 1];
__device__ int   g_cur[NMAX];
__device__ int   g_srcs[EMAX];
__device__ int   g_bsums[(NMAX + SCAN_CHUNK - 1) / SCAN_CHUNK];
__device__ int   g_boff [(NMAX + SCAN_CHUNK - 1) / SCAN_CHUNK];
__device__ int   g_is64;

// ---------------------------------------------------------------------------
// Detect whether edge_index is stored as int64 (high words zero) or int32.
// ---------------------------------------------------------------------------
__global__ __launch_bounds__(256)
void detect_kernel(const int* __restrict__ ei)
{
    __shared__ int s_or;
    if (threadIdx.x == 0) s_or = 0;
    __syncthreads();
    int o = 0;
    for (int i = threadIdx.x; i < 2048; i += 256)
        o |= ei[2 * i + 1];
    if (o) atomicOr(&s_or, 1);
    __syncthreads();
    if (threadIdx.x == 0) g_is64 = (s_or == 0) ? 1 : 0;
}

__device__ __forceinline__ int load_src(const int* ei, int E, int i, int is64)
{
    return is64 ? ei[2 * i] : ei[i];
}
__device__ __forceinline__ int load_dst(const int* ei, int E, int i, int is64)
{
    return is64 ? ei[2 * E + 2 * i] : ei[E + i];
}

// ---------------------------------------------------------------------------
// CSR build (by destination). Only integer atomics.
// ---------------------------------------------------------------------------
__global__ __launch_bounds__(256)
void zero_cnt_kernel(int n)
{
    int i = blockIdx.x * blockDim.x + threadIdx.x;
    if (i < n) g_cnt[i] = 0;
}

__global__ __launch_bounds__(256)
void hist_kernel(const int* __restrict__ ei, int E)
{
    int i = blockIdx.x * blockDim.x + threadIdx.x;
    int is64 = g_is64;
    if (i < E) atomicAdd(&g_cnt[load_dst(ei, E, i, is64)], 1);
}

__device__ __forceinline__ int block_exscan256(int v, int* sh)
{
    const int t = threadIdx.x;
    sh[t] = v;
    __syncthreads();
#pragma unroll
    for (int off = 1; off < 256; off <<= 1) {
        int u = (t >= off) ? sh[t - off] : 0;
        __syncthreads();
        sh[t] += u;
        __syncthreads();
    }
    return sh[t] - v;
}

__global__ __launch_bounds__(256)
void scan_partial(int n)
{
    __shared__ int sh[256];
    const int t = threadIdx.x;
    const int base = blockIdx.x * SCAN_CHUNK + t * 4;
    int s = 0;
#pragma unroll
    for (int j = 0; j < 4; j++)
        if (base + j < n) s += g_cnt[base + j];
    sh[t] = s;
    __syncthreads();
    for (int off = 128; off; off >>= 1) {
        if (t < off) sh[t] += sh[t + off];
        __syncthreads();
    }
    if (t == 0) g_bsums[blockIdx.x] = sh[0];
}

__global__ __launch_bounds__(256)
void scan_bsums(int nb)
{
    __shared__ int sh[256];
    const int t = threadIdx.x;
    int v = (t < nb) ? g_bsums[t] : 0;
    int ex = block_exscan256(v, sh);
    if (t < nb) g_boff[t] = ex;
}

__global__ __launch_bounds__(256)
void scan_final(int n, int E)
{
    __shared__ int sh[256];
    const int t = threadIdx.x;
    const int base = blockIdx.x * SCAN_CHUNK + t * 4;
    int c[4];
    int s = 0;
#pragma unroll
    for (int j = 0; j < 4; j++) {
        c[j] = (base + j < n) ? g_cnt[base + j] : 0;
        s += c[j];
    }
    int ex = block_exscan256(s, sh) + g_boff[blockIdx.x];
#pragma unroll
    for (int j = 0; j < 4; j++) {
        if (base + j < n) {
            g_off[base + j] = ex;
            g_cur[base + j] = ex;
        }
        ex += c[j];
    }
    if (blockIdx.x == 0 && t == 0) g_off[n] = E;
}

__global__ __launch_bounds__(256)
void scatter_kernel(const int* __restrict__ ei, int E)
{
    int i = blockIdx.x * blockDim.x + threadIdx.x;
    if (i >= E) return;
    int is64 = g_is64;
    int d = load_dst(ei, E, i, is64);
    int s = load_src(ei, E, i, is64);
    int pos = atomicAdd(&g_cur[d], 1);
    g_srcs[pos] = s;
}

// ---------------------------------------------------------------------------
// Fused GEMM + attention-logit epilogue. LAYER selects the output buffer set
// (1: g_xp1/g_als1/g_ald1 reading external X; 2: g_xp2/... reading g_h).
// row_base allows chunked launches.
// ---------------------------------------------------------------------------
template<int K, int LAYER>
__global__ __launch_bounds__(256)
void gemm_al_kernel(const float* __restrict__ Xin,
                    const float* __restrict__ W,
                    const float* __restrict__ att_s,
                    const float* __restrict__ att_d,
                    int n, int row_base)
{
    const float* __restrict__ X = (LAYER == 1) ? Xin : g_h;
    __half* __restrict__ xp  = (LAYER == 1) ? g_xp1 : g_xp2;
    float*  __restrict__ als = (LAYER == 1) ? g_als1 : g_als2;
    float*  __restrict__ ald = (LAYER == 1) ? g_ald1 : g_ald2;

    __shared__ __align__(16) float sW[64 * 64];
    __shared__ __align__(16) float sXT[64][132];

    const int tid = threadIdx.x;
    const int cx  = tid & 15;
    const int ry  = tid >> 4;
    const int row0 = row_base + blockIdx.x * 128;

    float C[8][4];
#pragma unroll
    for (int i = 0; i < 8; i++)
#pragma unroll
        for (int j = 0; j < 4; j++) C[i][j] = 0.f;

    for (int kc = 0; kc < K; kc += 64) {
        __syncthreads();
#pragma unroll
        for (int q = 0; q < 4; q++) {
            int idx4 = tid + q * 256;
            float4 v = *(const float4*)&W[kc * 64 + idx4 * 4];
            *(float4*)&sW[idx4 * 4] = v;
        }
#pragma unroll
        for (int q = 0; q < 8; q++) {
            int lin = tid + q * 256;
            int r  = lin >> 4;
            int c4 = lin & 15;
            int gr = row0 + r; if (gr > n - 1) gr = n - 1;
            float4 v = *(const float4*)&X[(long long)gr * K + kc + c4 * 4];
            sXT[c4 * 4 + 0][r] = v.x;
            sXT[c4 * 4 + 1][r] = v.y;
            sXT[c4 * 4 + 2][r] = v.z;
            sXT[c4 * 4 + 3][r] = v.w;
        }
        __syncthreads();
#pragma unroll
        for (int k = 0; k < 64; k++) {
            float4 wv = *(const float4*)&sW[k * 64 + cx * 4];
            float4 xa = *(const float4*)&sXT[k][ry * 8];
            float4 xb = *(const float4*)&sXT[k][ry * 8 + 4];
            float xr[8] = {xa.x, xa.y, xa.z, xa.w, xb.x, xb.y, xb.z, xb.w};
#pragma unroll
            for (int i = 0; i < 8; i++) {
                C[i][0] = fmaf(xr[i], wv.x, C[i][0]);
                C[i][1] = fmaf(xr[i], wv.y, C[i][1]);
                C[i][2] = fmaf(xr[i], wv.z, C[i][2]);
                C[i][3] = fmaf(xr[i], wv.w, C[i][3]);
            }
        }
    }

    const int h    = cx >> 3;
    const int lane = tid & 31;
    float asv[4], adv[4];
#pragma unroll
    for (int j = 0; j < 4; j++) {
        asv[j] = __ldg(&att_s[cx * 4 + j]);
        adv[j] = __ldg(&att_d[cx * 4 + j]);
    }

#pragma unroll
    for (int i = 0; i < 8; i++) {
        float alsv = 0.f, aldv = 0.f;
#pragma unroll
        for (int j = 0; j < 4; j++) {
            alsv = fmaf(C[i][j], asv[j], alsv);
            aldv = fmaf(C[i][j], adv[j], aldv);
        }
#pragma unroll
        for (int off = 4; off; off >>= 1) {
            alsv += __shfl_down_sync(0xffffffffu, alsv, off, 8);
            aldv += __shfl_down_sync(0xffffffffu, aldv, off, 8);
        }
        int row = row0 + ry * 8 + i;
        if (row < n) {
            if ((lane & 7) == 0) {
                als[row * 2 + h] = alsv;
                ald[row * 2 + h] = aldv;
            }
            __half2 p0 = __floats2half2_rn(C[i][0], C[i][1]);
            __half2 p1 = __floats2half2_rn(C[i][2], C[i][3]);
            __half2* dst = reinterpret_cast<__half2*>(&xp[row * HID + cx * 4]);
            dst[0] = p0;
            dst[1] = p1;
        }
    }
}

// ---------------------------------------------------------------------------
// Gather pass (204.9us winner, v3), buffer-parameterized by LAYER.
// ---------------------------------------------------------------------------
template<int LAYER>
__global__ __launch_bounds__(256)
void gather_kernel(const float* __restrict__ bias,
                   float* __restrict__ out, int node0, int node1)
{
    const __half* __restrict__ xp  = (LAYER == 1) ? g_xp1 : g_xp2;
    const float*  __restrict__ als = (LAYER == 1) ? g_als1 : g_als2;
    const float*  __restrict__ ald = (LAYER == 1) ? g_ald1 : g_ald2;

    int warp = (blockIdx.x * 256 + threadIdx.x) >> 5;
    int lane = threadIdx.x & 31;
    int node = node0 + warp;
    if (node >= node1) return;
    const int h  = lane >> 4;           // half-warp = head
    const int hl = lane & 15;           // lane within half

    const __half2* __restrict__ xp2 =
        reinterpret_cast<const __half2*>(xp) + lane;  // + 32*s per row

    const float ald_h = __ldg(&ald[node * 2 + h]);

    // self loop
    float t0 = __ldg(&als[node * 2 + h]) + ald_h;
    t0 = fmaxf(t0, 0.2f * t0);
    float wself = __expf(t0);
    float2 xv = __half22float2(xp2[node * 32]);
    float a0 = xv.x * wself, a1 = xv.y * wself;
    float segl = 0.f;

    const int beg = g_off[node];
    const int end = g_off[node + 1];
    for (int i = beg; i < end; i += 16) {
        int idx = i + hl;
        bool valid = idx < end;
        int sidx = valid ? __ldg(&g_srcs[idx]) : 0;
        float al = __ldg(&als[sidx * 2 + h]);
        float tt = al + ald_h;
        tt = fmaxf(tt, 0.2f * tt);
        float w = valid ? __expf(tt) : 0.f;
        segl += w;

#pragma unroll
        for (int jb = 0; jb < 16; jb += 8) {
            float  ww[8];
            float2 xs[8];
#pragma unroll
            for (int j = 0; j < 8; j++) {
                ww[j] = __shfl_sync(0xffffffffu, w,    jb + j, 16);
                int s = __shfl_sync(0xffffffffu, sidx, jb + j, 16);
                xs[j] = __half22float2(xp2[s * 32]);
            }
#pragma unroll
            for (int j = 0; j < 8; j++) {
                a0 = fmaf(xs[j].x, ww[j], a0);
                a1 = fmaf(xs[j].y, ww[j], a1);
            }
        }
    }

#pragma unroll
    for (int off = 8; off; off >>= 1)
        segl += __shfl_xor_sync(0xffffffffu, segl, off, 16);
    float seg = segl + wself;

    float inv = 1.f / (seg + 1e-16f);
    float2 bv = *(const float2*)&bias[lane * 2];
    float v0 = a0 * inv + bv.x;
    float v1 = a1 * inv + bv.y;
    if (LAYER == 1) {
        v0 = v0 > 0.f ? v0 : expm1f(v0);
        v1 = v1 > 0.f ? v1 : expm1f(v1);
        *(float2*)&g_h[node * HID + lane * 2] = make_float2(v0, v1);
    } else {
        *(float2*)&out[node * HID + lane * 2] = make_float2(v0, v1);
    }
}

extern "C" void kernel_launch(void* const* d_in, const int* in_sizes, int n_in,
                              void* d_out, int out_size)
{
    const float* x   = (const float*)d_in[0];
    const int*   ei  = (const int*)d_in[1];
    const float* W1  = (const float*)d_in[2];
    const float* as1 = (const float*)d_in[3];
    const float* ad1 = (const float*)d_in[4];
    const float* b1  = (const float*)d_in[5];
    const float* W2  = (const float*)d_in[6];
    const float* as2 = (const float*)d_in[7];
    const float* ad2 = (const float*)d_in[8];
    const float* b2  = (const float*)d_in[9];

    const int n = in_sizes[0] / 128;          // 100000
    const int E = in_sizes[1] / 2;            // 1600000
    const int nbl = (n + 255) / 256;
    const int ebl = (E + 255) / 256;
    const int sb  = (n + SCAN_CHUNK - 1) / SCAN_CHUNK;

    // chunk split for gather1/gemm2 pipelining (multiple of 128)
    const int nA  = ((n / 2 + 127) / 128) * 128;   // 50048
    const int gbF = (n + 127) / 128;
    const int gbA = nA / 128;
    const int gbB = (n - nA + 127) / 128;
    const int wblA = (nA * 32 + 255) / 256;
    const int wblB = ((n - nA) * 32 + 255) / 256;
    const int wblF = (n * 32 + 255) / 256;

    static cudaStream_t sCsr = nullptr, sMain = nullptr;
    static cudaEvent_t evFork = nullptr, evCsr = nullptr, evA = nullptr,
                       evB = nullptr, evDone = nullptr;
    if (!sCsr) {
        cudaStreamCreateWithFlags(&sCsr,  cudaStreamNonBlocking);
        cudaStreamCreateWithFlags(&sMain, cudaStreamNonBlocking);
        cudaEventCreateWithFlags(&evFork, cudaEventDisableTiming);
        cudaEventCreateWithFlags(&evCsr,  cudaEventDisableTiming);
        cudaEventCreateWithFlags(&evA,    cudaEventDisableTiming);
        cudaEventCreateWithFlags(&evB,    cudaEventDisableTiming);
        cudaEventCreateWithFlags(&evDone, cudaEventDisableTiming);
    }

    cudaEventRecord(evFork, 0);
    cudaStreamWaitEvent(sCsr,  evFork, 0);
    cudaStreamWaitEvent(sMain, evFork, 0);

    // CSR chain on sCsr; gemm1 concurrently on sMain
    detect_kernel<<<1, 256, 0, sCsr>>>(ei);
    zero_cnt_kernel<<<nbl, 256, 0, sCsr>>>(n);
    hist_kernel<<<ebl, 256, 0, sCsr>>>(ei, E);
    gemm_al_kernel<128, 1><<<gbF, 256, 0, sMain>>>(x, W1, as1, ad1, n, 0);
    scan_partial<<<sb, 256, 0, sCsr>>>(n);
    scan_bsums<<<1, 256, 0, sCsr>>>(sb);
    scan_final<<<sb, 256, 0, sCsr>>>(n, E);
    scatter_kernel<<<ebl, 256, 0, sCsr>>>(ei, E);
    cudaEventRecord(evCsr, sCsr);

    // gather1 chunk A (needs gemm1 + CSR)
    cudaStreamWaitEvent(sMain, evCsr, 0);
    gather_kernel<1><<<wblA, 256, 0, sMain>>>(b1, nullptr, 0, nA);
    cudaEventRecord(evA, sMain);

    // gather1 chunk B on sCsr, overlapping gemm2(A) on sMain.
    // Safe: gather1 touches only layer-1 buffers; gemm2 writes layer-2 buffers.
    cudaStreamWaitEvent(sCsr, evA, 0);
    gather_kernel<1><<<wblB, 256, 0, sCsr>>>(b1, nullptr, nA, n);
    cudaEventRecord(evB, sCsr);

    // gemm2 chunk A (g_h rows [0,nA) ready)
    gemm_al_kernel<64, 2><<<gbA, 256, 0, sMain>>>(x, W2, as2, ad2, n, 0);
    // gemm2 chunk B after gather1(B) produced g_h rows [nA,n)
    cudaStreamWaitEvent(sMain, evB, 0);
    gemm_al_kernel<64, 2><<<gbB, 256, 0, sMain>>>(x, W2, as2, ad2, n, nA);
    // gather2 (full)
    gather_kernel<2><<<wblF, 256, 0, sMain>>>(b2, (float*)d_out, 0, n);

    cudaEventRecord(evDone, sMain);
    cudaStreamWaitEvent(0, evDone, 0);
}